// round 13
// baseline (speedup 1.0000x reference)
#include <cuda_runtime.h>
#include <cuda_bf16.h>
#include <math.h>
#include <cstdint>

// ---------------- problem constants ----------------
#define NB      4
#define LQ      4096
#define DM      256
#define NH      8
#define NL      4
#define NP      4
#define DH      32
#define S_TOT   7680
#define HLP     128
#define MQ      (NB*LQ)     // 16384
#define MV      (NB*S_TOT)  // 30720

// ---------------- scratch (static device memory) ----------------
__device__ float g_value[MV * DM];     // value = flat @ W_v (fp32)
__device__ float g_oa  [MQ * 256];     // cols 0:128 = off, 128:256 = aw logits
__device__ float g_mid [MQ * DM];      // sampled output, tf32-rounded at store
__device__ float g_BtV [256 * 256];    // W_v^T   [N,K] K-major, tf32-rounded
__device__ float g_BtOA[256 * 256];    // [W_off^T ; W_aw^T],   tf32-rounded
__device__ float g_BtO [256 * 256];    // W_out^T,              tf32-rounded
__device__ float g_bOA [256];          // [b_off ; b_aw]

// ---------------- helpers ----------------
__device__ __forceinline__ uint32_t f2tf32(float f) {
    uint32_t r;
    asm("cvt.rna.tf32.f32 %0, %1;" : "=r"(r) : "f"(f));
    return r;
}
__device__ __forceinline__ uint32_t u2tf32(uint32_t u) {
    return f2tf32(__uint_as_float(u));
}

__device__ __forceinline__ void mma_tf32(float* c, const uint32_t* a,
                                         uint32_t b0, uint32_t b1) {
    asm volatile(
        "mma.sync.aligned.m16n8k8.row.col.f32.tf32.tf32.f32 "
        "{%0,%1,%2,%3}, {%4,%5,%6,%7}, {%8,%9}, {%0,%1,%2,%3};"
        : "+f"(c[0]), "+f"(c[1]), "+f"(c[2]), "+f"(c[3])
        : "r"(a[0]), "r"(a[1]), "r"(a[2]), "r"(a[3]), "r"(b0), "r"(b1));
}

// ldmatrix x4: four 8-row x 16B tiles, distributed lane 4r+c <- row r word c.
__device__ __forceinline__ void ldsm_x4(uint32_t* r, uint32_t addr) {
    asm volatile("ldmatrix.sync.aligned.m8n8.x4.shared.b16 {%0,%1,%2,%3}, [%4];"
                 : "=r"(r[0]), "=r"(r[1]), "=r"(r[2]), "=r"(r[3]) : "r"(addr));
}

__device__ __forceinline__ void cp16(uint32_t dst, const void* src) {
    asm volatile("cp.async.cg.shared.global [%0], [%1], 16;" :: "r"(dst), "l"(src));
}
#define CP_COMMIT() asm volatile("cp.async.commit_group;" ::: "memory")
#define CP_WAIT0()  asm volatile("cp.async.wait_group 0;"  ::: "memory")

// ---------------- tf32 mma.sync GEMM (R9 config + B-fragment pipelining) -----
// 128x128 tile, 256 threads (8 warps, warp tile 32x64), BK=32, double-buffered
// cp.async (.cg); LDSM.x4 fragments with B double-buffered in registers so
// each MMA group overlaps the next group's LDSM. RS=36 conflict-free.
#define RS 36
#define BUFW (128 * RS)
template<bool CVTA>
__global__ __launch_bounds__(256, 2)
void mma_gemm_kernel(const float* __restrict__ A0, const float* __restrict__ B0,
                     const float* __restrict__ bias0, float* __restrict__ C0,
                     int rows0,
                     const float* __restrict__ A1, const float* __restrict__ B1,
                     const float* __restrict__ bias1, float* __restrict__ C1)
{
    extern __shared__ uint32_t smu[];  // 4*BUFW words = 73728 B

    const float* A;  const float* Bt;  const float* bias;  float* C;
    int block_row;
    if ((int)blockIdx.y < rows0) {
        A = A0; Bt = B0; bias = bias0; C = C0; block_row = blockIdx.y * 128;
    } else {
        A = A1; Bt = B1; bias = bias1; C = C1; block_row = (blockIdx.y - rows0) * 128;
    }

    const int tid  = threadIdx.x;
    const int wid  = tid >> 5;
    const int lane = tid & 31;
    const int g8   = lane >> 2;
    const int t4   = lane & 3;
    const int block_col = blockIdx.x * 128;
    const int warp_m = (wid >> 1) * 32;
    const int warp_n = (wid & 1) * 64;

    const float* Ag = A  + (long)block_row * 256;
    const float* Bg = Bt + (long)block_col * 256;

    float acc[2][8][4];
    #pragma unroll
    for (int im = 0; im < 2; im++)
        #pragma unroll
        for (int in_ = 0; in_ < 8; in_++)
            #pragma unroll
            for (int q = 0; q < 4; q++)
                acc[im][in_][q] = 0.0f;

    const int cr[4] = { (tid + 0)   >> 3, (tid + 256) >> 3,
                        (tid + 512) >> 3, (tid + 768) >> 3 };
    const int cc = (tid & 7) * 4;

    uint32_t sbase;
    asm("{ .reg .u64 t; cvta.to.shared.u64 t, %1; cvt.u32.u64 %0, t; }"
        : "=r"(sbase) : "l"(smu));
    uint32_t soff[4];
    #pragma unroll
    for (int j = 0; j < 4; j++) soff[j] = (uint32_t)(cr[j] * RS + cc) * 4u;

    uint32_t aoff[2];
    #pragma unroll
    for (int im = 0; im < 2; im++)
        aoff[im] = (uint32_t)((warp_m + im * 16 + (lane & 15)) * RS
                              + (lane >> 4) * 4) * 4u;
    uint32_t boff[4];
    #pragma unroll
    for (int j = 0; j < 4; j++)
        boff[j] = (uint32_t)((warp_n + j * 16 + (lane & 7) + (lane >> 4) * 8) * RS
                             + ((lane >> 3) & 1) * 4) * 4u + BUFW * 4u;

    #pragma unroll
    for (int j = 0; j < 4; j++) {
        cp16(sbase + soff[j],            Ag + (long)cr[j] * 256 + cc);
        cp16(sbase + BUFW * 4 + soff[j], Bg + (long)cr[j] * 256 + cc);
    }
    CP_COMMIT();
    CP_WAIT0();
    __syncthreads();

    for (int it = 0; it < 8; ++it) {
        const uint32_t buf = sbase + (uint32_t)(it & 1) * (2 * BUFW) * 4u;
        const uint32_t nb  = sbase + (uint32_t)((it + 1) & 1) * (2 * BUFW) * 4u;

        if (it < 7) {
            const int k0 = (it + 1) * 32;
            #pragma unroll
            for (int j = 0; j < 4; j++) {
                cp16(nb + soff[j],            Ag + (long)cr[j] * 256 + k0 + cc);
                cp16(nb + BUFW * 4 + soff[j], Bg + (long)cr[j] * 256 + k0 + cc);
            }
            CP_COMMIT();
        }

        #pragma unroll
        for (int ks = 0; ks < 4; ks++) {
            const uint32_t kb = (uint32_t)(ks * 8) * 4u;
            uint32_t af[2][4];
            ldsm_x4(af[0], buf + aoff[0] + kb);
            ldsm_x4(af[1], buf + aoff[1] + kb);
            if (CVTA) {
                #pragma unroll
                for (int im = 0; im < 2; im++)
                    #pragma unroll
                    for (int q = 0; q < 4; q++)
                        af[im][q] = u2tf32(af[im][q]);
            }
            // B fragments double-buffered: LDSM of j+1 overlaps MMAs of j
            uint32_t bf[2][4];
            ldsm_x4(bf[0], buf + boff[0] + kb);
            #pragma unroll
            for (int j = 0; j < 4; j++) {
                if (j < 3) ldsm_x4(bf[(j + 1) & 1], buf + boff[j + 1] + kb);
                const uint32_t* b = bf[j & 1];
                mma_tf32(acc[0][2 * j    ], af[0], b[0], b[1]);
                mma_tf32(acc[0][2 * j + 1], af[0], b[2], b[3]);
                mma_tf32(acc[1][2 * j    ], af[1], b[0], b[1]);
                mma_tf32(acc[1][2 * j + 1], af[1], b[2], b[3]);
            }
        }

        if (it < 7) {
            CP_WAIT0();
            __syncthreads();
        }
    }

    #pragma unroll
    for (int im = 0; im < 2; im++) {
        const int r0 = block_row + warp_m + im * 16 + g8;
        #pragma unroll
        for (int in_ = 0; in_ < 8; in_++) {
            const int col = block_col + warp_n + in_ * 8 + 2 * t4;
            const float bx = bias[col], by = bias[col + 1];
            float2 o0 = make_float2(acc[im][in_][0] + bx, acc[im][in_][1] + by);
            float2 o1 = make_float2(acc[im][in_][2] + bx, acc[im][in_][3] + by);
            *(float2*)(C + (long)r0 * 256 + col)       = o0;
            *(float2*)(C + (long)(r0 + 8) * 256 + col) = o1;
        }
    }
}

// ---------------- fused prep: 4 transposes (tf32-round) + bias concat --------
__global__ void prep_kernel(const float* __restrict__ W_v,
                            const float* __restrict__ W_off,
                            const float* __restrict__ W_aw,
                            const float* __restrict__ W_out,
                            const float* __restrict__ b_off,
                            const float* __restrict__ b_aw)
{
    const int b = blockIdx.x;
    if (b == 192) {
        int t = threadIdx.y * 32 + threadIdx.x;
        if (t < 256) g_bOA[t] = (t < 128) ? b_off[t] : b_aw[t - 128];
        return;
    }
    const float* W; float* Bt; int N, rowoff, local;
    if (b < 64)       { W = W_v;   Bt = g_BtV;  N = 256; rowoff = 0;   local = b; }
    else if (b < 96)  { W = W_off; Bt = g_BtOA; N = 128; rowoff = 0;   local = b - 64; }
    else if (b < 128) { W = W_aw;  Bt = g_BtOA; N = 128; rowoff = 128; local = b - 96; }
    else              { W = W_out; Bt = g_BtO;  N = 256; rowoff = 0;   local = b - 128; }
    const int nx = N / 32;
    const int n0 = (local % nx) * 32;
    const int k0 = (local / nx) * 32;

    __shared__ float t[32][33];
    t[threadIdx.y][threadIdx.x] = W[(k0 + threadIdx.y) * N + n0 + threadIdx.x];
    __syncthreads();
    Bt[(long)(rowoff + n0 + threadIdx.y) * 256 + k0 + threadIdx.x] =
        __uint_as_float(f2tf32(t[threadIdx.x][threadIdx.y]));
}

// ---------------- sampling kernel v4 -----------------------------------------
// Block = 4 queries, 256 threads. Phase 1: two passes of 128 threads/query,
// one thread per (head,point), width-16 shuffle softmax (logits O(1), no max
// subtraction). Phase 2: 8 warps x 4 (query,head) tasks -> 4x gather MLP.
__global__ __launch_bounds__(256)
void msda_sample_kernel(const float* __restrict__ ref,
                        const int*   __restrict__ shapes,
                        const int*   __restrict__ start)
{
    __shared__ float4 sp[4][NH][16];

    const int q0  = blockIdx.x * 4;
    const int tid = threadIdx.x;

    // ---- phase 1: one thread per (query, head, point), 2 passes ----
    #pragma unroll
    for (int p = 0; p < 2; p++) {
        const int ql = (tid >> 7) + 2 * p;    // 0..3
        const int t  = tid & 127;
        const int nq = q0 + ql;
        const int n  = nq / LQ;
        const int m  = t >> 4;
        const int lp = t & 15;
        const int l  = lp >> 2;

        const int   Ti = shapes[l];
        const float Tf = (float)Ti;
        const int   st = start[l];

        const float offv  = g_oa[(long)nq * 256 +       m * 16 + lp];
        const float logit = g_oa[(long)nq * 256 + 128 + m * 16 + lp];
        const float r     = ref[(long)nq * NL + l];

        float x  = fminf(fmaxf(r * Tf + offv - 0.5f, 0.0f), Tf - 1.0f);
        float x0 = floorf(x);
        float w  = x - x0;
        int   i0 = (int)x0;
        int   i1 = min(i0 + 1, Ti - 1);
        int   g0 = (n * S_TOT + st + i0) * DM + m * DH;
        int   g1 = (n * S_TOT + st + i1) * DM + m * DH;

        float e = expf(logit);
        float ssum = e;
        #pragma unroll
        for (int o = 8; o > 0; o >>= 1)
            ssum += __shfl_xor_sync(0xffffffffu, ssum, o, 16);
        float aw = e / ssum;

        sp[ql][m][lp] = make_float4(__int_as_float(g0), __int_as_float(g1), w, aw);
    }
    __syncthreads();

    // ---- phase 2: warp wid handles tasks wid*4 .. wid*4+3 (task = q*8+h) ----
    const int wid  = tid >> 5;
    const int lane = tid & 31;
    const int g    = lane >> 3;
    const int c    = lane & 7;

    #pragma unroll
    for (int h2 = 0; h2 < 4; h2++) {
        const int task = wid * 4 + h2;      // 0..31
        const int qw   = task >> 3;
        const int mh   = task & 7;
        float4 acc = make_float4(0.f, 0.f, 0.f, 0.f);
        #pragma unroll
        for (int t = 0; t < 4; t++) {
            float4 pr = sp[qw][mh][t * 4 + g];
            int   ig0 = __float_as_int(pr.x);
            int   ig1 = __float_as_int(pr.y);
            float w   = pr.z;
            float aw  = pr.w;
            float4 v0 = *(const float4*)(g_value + ig0 + c * 4);
            float4 v1 = *(const float4*)(g_value + ig1 + c * 4);
            acc.x = fmaf(aw, fmaf(w, v1.x - v0.x, v0.x), acc.x);
            acc.y = fmaf(aw, fmaf(w, v1.y - v0.y, v0.y), acc.y);
            acc.z = fmaf(aw, fmaf(w, v1.z - v0.z, v0.z), acc.z);
            acc.w = fmaf(aw, fmaf(w, v1.w - v0.w, v0.w), acc.w);
        }
        #pragma unroll
        for (int o = 8; o <= 16; o <<= 1) {
            acc.x += __shfl_xor_sync(0xffffffffu, acc.x, o);
            acc.y += __shfl_xor_sync(0xffffffffu, acc.y, o);
            acc.z += __shfl_xor_sync(0xffffffffu, acc.z, o);
            acc.w += __shfl_xor_sync(0xffffffffu, acc.w, o);
        }
        if (lane < 8) {
            acc.x = __uint_as_float(f2tf32(acc.x));
            acc.y = __uint_as_float(f2tf32(acc.y));
            acc.z = __uint_as_float(f2tf32(acc.z));
            acc.w = __uint_as_float(f2tf32(acc.w));
            *(float4*)(g_mid + (long)(q0 + qw) * DM + mh * DH + c * 4) = acc;
        }
    }
}

// ---------------- launch ------------------------------------------------------
extern "C" void kernel_launch(void* const* d_in, const int* in_sizes, int n_in,
                              void* d_out, int out_size)
{
    const float* query  = (const float*)d_in[0];
    const float* refpts = (const float*)d_in[1];
    const float* flat   = (const float*)d_in[2];
    const int*   shapes = (const int*)  d_in[3];
    const int*   start  = (const int*)  d_in[4];
    const float* W_off  = (const float*)d_in[5];
    const float* b_off  = (const float*)d_in[6];
    const float* W_aw   = (const float*)d_in[7];
    const float* b_aw   = (const float*)d_in[8];
    const float* W_v    = (const float*)d_in[9];
    const float* b_v    = (const float*)d_in[10];
    const float* W_out  = (const float*)d_in[11];
    const float* b_out  = (const float*)d_in[12];
    float* out = (float*)d_out;

    float *p_value, *p_oa, *p_mid, *p_BtV, *p_BtOA, *p_BtO, *p_bOA;
    cudaGetSymbolAddress((void**)&p_value, g_value);
    cudaGetSymbolAddress((void**)&p_oa,    g_oa);
    cudaGetSymbolAddress((void**)&p_mid,   g_mid);
    cudaGetSymbolAddress((void**)&p_BtV,   g_BtV);
    cudaGetSymbolAddress((void**)&p_BtOA,  g_BtOA);
    cudaGetSymbolAddress((void**)&p_BtO,   g_BtO);
    cudaGetSymbolAddress((void**)&p_bOA,   g_bOA);

    const int smem_bytes = 4 * BUFW * 4;   // 73728
    cudaFuncSetAttribute(mma_gemm_kernel<true>,
                         cudaFuncAttributeMaxDynamicSharedMemorySize, smem_bytes);
    cudaFuncSetAttribute(mma_gemm_kernel<false>,
                         cudaFuncAttributeMaxDynamicSharedMemorySize, smem_bytes);

    // prep: weight transposes (tf32-rounded) + bias concat
    prep_kernel<<<193, dim3(32, 32)>>>(W_v, W_off, W_aw, W_out, b_off, b_aw);

    // fused GEMM1: value = flat@BtV + b_v  |  [off|aw] = query@BtOA + bOA
    mma_gemm_kernel<true><<<dim3(2, MV / 128 + MQ / 128), 256, smem_bytes>>>(
        flat, p_BtV, b_v, p_value, MV / 128,
        query, p_BtOA, p_bOA, p_oa);

    // sampling (4 queries per block; writes tf32-rounded g_mid)
    msda_sample_kernel<<<MQ / 4, 256>>>(refpts, shapes, start);

    // GEMM2: out = mid @ BtO + b_out (A already tf32 -> raw fragments)
    mma_gemm_kernel<false><<<dim3(2, MQ / 128), 256, smem_bytes>>>(
        p_mid, p_BtO, b_out, out, MQ / 128,
        p_mid, p_BtO, b_out, out);
}

// round 14
// speedup vs baseline: 1.0580x; 1.0580x over previous
#include <cuda_runtime.h>
#include <cuda_bf16.h>
#include <math.h>
#include <cstdint>

// ---------------- problem constants ----------------
#define NB      4
#define LQ      4096
#define DM      256
#define NH      8
#define NL      4
#define NP      4
#define DH      32
#define S_TOT   7680
#define HLP     128
#define MQ      (NB*LQ)     // 16384
#define MV      (NB*S_TOT)  // 30720

// ---------------- scratch (static device memory) ----------------
__device__ float g_value[MV * DM];     // value = flat @ W_v (fp32)
__device__ float g_oa  [MQ * 256];     // cols 0:128 = off, 128:256 = aw logits
__device__ float g_mid [MQ * DM];      // sampled output, tf32-rounded at store
__device__ float g_BtV [256 * 256];    // W_v^T   [N,K] K-major, tf32-rounded
__device__ float g_BtOA[256 * 256];    // [W_off^T ; W_aw^T],   tf32-rounded
__device__ float g_BtO [256 * 256];    // W_out^T,              tf32-rounded
__device__ float g_bOA [256];          // [b_off ; b_aw]

// ---------------- helpers ----------------
__device__ __forceinline__ uint32_t f2tf32(float f) {
    uint32_t r;
    asm("cvt.rna.tf32.f32 %0, %1;" : "=r"(r) : "f"(f));
    return r;
}
__device__ __forceinline__ uint32_t u2tf32(uint32_t u) {
    return f2tf32(__uint_as_float(u));
}

__device__ __forceinline__ void mma_tf32(float* c, const uint32_t* a,
                                         uint32_t b0, uint32_t b1) {
    asm volatile(
        "mma.sync.aligned.m16n8k8.row.col.f32.tf32.tf32.f32 "
        "{%0,%1,%2,%3}, {%4,%5,%6,%7}, {%8,%9}, {%0,%1,%2,%3};"
        : "+f"(c[0]), "+f"(c[1]), "+f"(c[2]), "+f"(c[3])
        : "r"(a[0]), "r"(a[1]), "r"(a[2]), "r"(a[3]), "r"(b0), "r"(b1));
}

// ldmatrix x4: four 8-row x 16B tiles, distributed lane 4r+c <- row r word c.
__device__ __forceinline__ void ldsm_x4(uint32_t* r, uint32_t addr) {
    asm volatile("ldmatrix.sync.aligned.m8n8.x4.shared.b16 {%0,%1,%2,%3}, [%4];"
                 : "=r"(r[0]), "=r"(r[1]), "=r"(r[2]), "=r"(r[3]) : "r"(addr));
}

__device__ __forceinline__ void cp16(uint32_t dst, const void* src) {
    asm volatile("cp.async.ca.shared.global [%0], [%1], 16;" :: "r"(dst), "l"(src));
}
#define CP_COMMIT() asm volatile("cp.async.commit_group;" ::: "memory")
#define CP_WAIT0()  asm volatile("cp.async.wait_group 0;"  ::: "memory")

// ---------------- tf32 mma.sync GEMM (R12 config + B-frag double-buffer) -----
// 128x128 tile, 256 threads (8 warps, warp tile 32x64), BK=32, double-buffered
// cp.async (.ca: B tiles hit L1 across CTAs); LDSM.x4 fragments; B fragments
// double-buffered in registers so each MMA group overlaps the next LDSM.
// RS=36 conflict-free. CVTA: cvt.rna on A fragments (A raw fp32 in smem).
#define RS 36
#define BUFW (128 * RS)
template<bool CVTA>
__global__ __launch_bounds__(256)
void mma_gemm_kernel(const float* __restrict__ A0, const float* __restrict__ B0,
                     const float* __restrict__ bias0, float* __restrict__ C0,
                     int rows0,
                     const float* __restrict__ A1, const float* __restrict__ B1,
                     const float* __restrict__ bias1, float* __restrict__ C1)
{
    extern __shared__ uint32_t smu[];  // 4*BUFW words = 73728 B

    const float* A;  const float* Bt;  const float* bias;  float* C;
    int block_row;
    if ((int)blockIdx.y < rows0) {
        A = A0; Bt = B0; bias = bias0; C = C0; block_row = blockIdx.y * 128;
    } else {
        A = A1; Bt = B1; bias = bias1; C = C1; block_row = (blockIdx.y - rows0) * 128;
    }

    const int tid  = threadIdx.x;
    const int wid  = tid >> 5;
    const int lane = tid & 31;
    const int g8   = lane >> 2;
    const int t4   = lane & 3;
    const int block_col = blockIdx.x * 128;
    const int warp_m = (wid >> 1) * 32;
    const int warp_n = (wid & 1) * 64;

    const float* Ag = A  + (long)block_row * 256;
    const float* Bg = Bt + (long)block_col * 256;

    float acc[2][8][4];
    #pragma unroll
    for (int im = 0; im < 2; im++)
        #pragma unroll
        for (int in_ = 0; in_ < 8; in_++)
            #pragma unroll
            for (int q = 0; q < 4; q++)
                acc[im][in_][q] = 0.0f;

    const int cr[4] = { (tid + 0)   >> 3, (tid + 256) >> 3,
                        (tid + 512) >> 3, (tid + 768) >> 3 };
    const int cc = (tid & 7) * 4;

    uint32_t sbase;
    asm("{ .reg .u64 t; cvta.to.shared.u64 t, %1; cvt.u32.u64 %0, t; }"
        : "=r"(sbase) : "l"(smu));
    uint32_t soff[4];
    #pragma unroll
    for (int j = 0; j < 4; j++) soff[j] = (uint32_t)(cr[j] * RS + cc) * 4u;

    uint32_t aoff[2];
    #pragma unroll
    for (int im = 0; im < 2; im++)
        aoff[im] = (uint32_t)((warp_m + im * 16 + (lane & 15)) * RS
                              + (lane >> 4) * 4) * 4u;
    uint32_t boff[4];
    #pragma unroll
    for (int j = 0; j < 4; j++)
        boff[j] = (uint32_t)((warp_n + j * 16 + (lane & 7) + (lane >> 4) * 8) * RS
                             + ((lane >> 3) & 1) * 4) * 4u + BUFW * 4u;

    #pragma unroll
    for (int j = 0; j < 4; j++) {
        cp16(sbase + soff[j],            Ag + (long)cr[j] * 256 + cc);
        cp16(sbase + BUFW * 4 + soff[j], Bg + (long)cr[j] * 256 + cc);
    }
    CP_COMMIT();
    CP_WAIT0();
    __syncthreads();

    for (int it = 0; it < 8; ++it) {
        const uint32_t buf = sbase + (uint32_t)(it & 1) * (2 * BUFW) * 4u;
        const uint32_t nb  = sbase + (uint32_t)((it + 1) & 1) * (2 * BUFW) * 4u;

        if (it < 7) {
            const int k0 = (it + 1) * 32;
            #pragma unroll
            for (int j = 0; j < 4; j++) {
                cp16(nb + soff[j],            Ag + (long)cr[j] * 256 + k0 + cc);
                cp16(nb + BUFW * 4 + soff[j], Bg + (long)cr[j] * 256 + k0 + cc);
            }
            CP_COMMIT();
        }

        #pragma unroll
        for (int ks = 0; ks < 4; ks++) {
            const uint32_t kb = (uint32_t)(ks * 8) * 4u;
            uint32_t af[2][4];
            ldsm_x4(af[0], buf + aoff[0] + kb);
            ldsm_x4(af[1], buf + aoff[1] + kb);
            if (CVTA) {
                #pragma unroll
                for (int im = 0; im < 2; im++)
                    #pragma unroll
                    for (int q = 0; q < 4; q++)
                        af[im][q] = u2tf32(af[im][q]);
            }
            // B fragments double-buffered: LDSM of j+1 overlaps MMAs of j
            uint32_t bf[2][4];
            ldsm_x4(bf[0], buf + boff[0] + kb);
            #pragma unroll
            for (int j = 0; j < 4; j++) {
                if (j < 3) ldsm_x4(bf[(j + 1) & 1], buf + boff[j + 1] + kb);
                const uint32_t* b = bf[j & 1];
                mma_tf32(acc[0][2 * j    ], af[0], b[0], b[1]);
                mma_tf32(acc[0][2 * j + 1], af[0], b[2], b[3]);
                mma_tf32(acc[1][2 * j    ], af[1], b[0], b[1]);
                mma_tf32(acc[1][2 * j + 1], af[1], b[2], b[3]);
            }
        }

        if (it < 7) {
            CP_WAIT0();
            __syncthreads();
        }
    }

    #pragma unroll
    for (int im = 0; im < 2; im++) {
        const int r0 = block_row + warp_m + im * 16 + g8;
        #pragma unroll
        for (int in_ = 0; in_ < 8; in_++) {
            const int col = block_col + warp_n + in_ * 8 + 2 * t4;
            const float bx = bias[col], by = bias[col + 1];
            float2 o0 = make_float2(acc[im][in_][0] + bx, acc[im][in_][1] + by);
            float2 o1 = make_float2(acc[im][in_][2] + bx, acc[im][in_][3] + by);
            *(float2*)(C + (long)r0 * 256 + col)       = o0;
            *(float2*)(C + (long)(r0 + 8) * 256 + col) = o1;
        }
    }
}

// ---------------- fused prep: 4 transposes (tf32-round) + bias concat --------
__global__ void prep_kernel(const float* __restrict__ W_v,
                            const float* __restrict__ W_off,
                            const float* __restrict__ W_aw,
                            const float* __restrict__ W_out,
                            const float* __restrict__ b_off,
                            const float* __restrict__ b_aw)
{
    const int b = blockIdx.x;
    if (b == 192) {
        int t = threadIdx.y * 32 + threadIdx.x;
        if (t < 256) g_bOA[t] = (t < 128) ? b_off[t] : b_aw[t - 128];
        return;
    }
    const float* W; float* Bt; int N, rowoff, local;
    if (b < 64)       { W = W_v;   Bt = g_BtV;  N = 256; rowoff = 0;   local = b; }
    else if (b < 96)  { W = W_off; Bt = g_BtOA; N = 128; rowoff = 0;   local = b - 64; }
    else if (b < 128) { W = W_aw;  Bt = g_BtOA; N = 128; rowoff = 128; local = b - 96; }
    else              { W = W_out; Bt = g_BtO;  N = 256; rowoff = 0;   local = b - 128; }
    const int nx = N / 32;
    const int n0 = (local % nx) * 32;
    const int k0 = (local / nx) * 32;

    __shared__ float t[32][33];
    t[threadIdx.y][threadIdx.x] = W[(k0 + threadIdx.y) * N + n0 + threadIdx.x];
    __syncthreads();
    Bt[(long)(rowoff + n0 + threadIdx.y) * 256 + k0 + threadIdx.x] =
        __uint_as_float(f2tf32(t[threadIdx.x][threadIdx.y]));
}

// ---------------- sampling kernel (exact R12 v3) ------------------------------
// Block = 2 queries, 256 threads. Phase 1: 128 threads per query, each owns
// one (head, level, point). Phase 2: 8 warps, 2 (query,head) tasks each.
__global__ __launch_bounds__(256)
void msda_sample_kernel(const float* __restrict__ ref,
                        const int*   __restrict__ shapes,
                        const int*   __restrict__ start)
{
    __shared__ float4 sp[2][NH][16];

    const int q0  = blockIdx.x * 2;
    const int tid = threadIdx.x;

    {
        const int ql = tid >> 7;
        const int t  = tid & 127;
        const int nq = q0 + ql;
        const int n  = nq / LQ;
        const int m  = t >> 4;
        const int lp = t & 15;
        const int l  = lp >> 2;

        const int   Ti = shapes[l];
        const float Tf = (float)Ti;
        const int   st = start[l];

        const float offv  = g_oa[(long)nq * 256 +       m * 16 + lp];
        const float logit = g_oa[(long)nq * 256 + 128 + m * 16 + lp];
        const float r     = ref[(long)nq * NL + l];

        float x  = fminf(fmaxf(r * Tf + offv - 0.5f, 0.0f), Tf - 1.0f);
        float x0 = floorf(x);
        float w  = x - x0;
        int   i0 = (int)x0;
        int   i1 = min(i0 + 1, Ti - 1);
        int   g0 = (n * S_TOT + st + i0) * DM + m * DH;
        int   g1 = (n * S_TOT + st + i1) * DM + m * DH;

        float e = expf(logit);
        float ssum = e;
        #pragma unroll
        for (int o = 8; o > 0; o >>= 1)
            ssum += __shfl_xor_sync(0xffffffffu, ssum, o, 16);
        float aw = e / ssum;

        sp[ql][m][lp] = make_float4(__int_as_float(g0), __int_as_float(g1), w, aw);
    }
    __syncthreads();

    const int wid  = tid >> 5;
    const int lane = tid & 31;
    const int qw   = wid >> 2;
    const int nq2  = q0 + qw;
    const int g    = lane >> 3;
    const int c    = lane & 7;

    #pragma unroll
    for (int h2 = 0; h2 < 2; h2++) {
        const int mh = (wid & 3) * 2 + h2;
        float4 acc = make_float4(0.f, 0.f, 0.f, 0.f);
        #pragma unroll
        for (int t = 0; t < 4; t++) {
            float4 pr = sp[qw][mh][t * 4 + g];
            int   ig0 = __float_as_int(pr.x);
            int   ig1 = __float_as_int(pr.y);
            float w   = pr.z;
            float aw  = pr.w;
            float4 v0 = *(const float4*)(g_value + ig0 + c * 4);
            float4 v1 = *(const float4*)(g_value + ig1 + c * 4);
            acc.x = fmaf(aw, fmaf(w, v1.x - v0.x, v0.x), acc.x);
            acc.y = fmaf(aw, fmaf(w, v1.y - v0.y, v0.y), acc.y);
            acc.z = fmaf(aw, fmaf(w, v1.z - v0.z, v0.z), acc.z);
            acc.w = fmaf(aw, fmaf(w, v1.w - v0.w, v0.w), acc.w);
        }
        #pragma unroll
        for (int o = 8; o <= 16; o <<= 1) {
            acc.x += __shfl_xor_sync(0xffffffffu, acc.x, o);
            acc.y += __shfl_xor_sync(0xffffffffu, acc.y, o);
            acc.z += __shfl_xor_sync(0xffffffffu, acc.z, o);
            acc.w += __shfl_xor_sync(0xffffffffu, acc.w, o);
        }
        if (lane < 8) {
            acc.x = __uint_as_float(f2tf32(acc.x));
            acc.y = __uint_as_float(f2tf32(acc.y));
            acc.z = __uint_as_float(f2tf32(acc.z));
            acc.w = __uint_as_float(f2tf32(acc.w));
            *(float4*)(g_mid + (long)nq2 * DM + mh * DH + c * 4) = acc;
        }
    }
}

// ---------------- launch ------------------------------------------------------
extern "C" void kernel_launch(void* const* d_in, const int* in_sizes, int n_in,
                              void* d_out, int out_size)
{
    const float* query  = (const float*)d_in[0];
    const float* refpts = (const float*)d_in[1];
    const float* flat   = (const float*)d_in[2];
    const int*   shapes = (const int*)  d_in[3];
    const int*   start  = (const int*)  d_in[4];
    const float* W_off  = (const float*)d_in[5];
    const float* b_off  = (const float*)d_in[6];
    const float* W_aw   = (const float*)d_in[7];
    const float* b_aw   = (const float*)d_in[8];
    const float* W_v    = (const float*)d_in[9];
    const float* b_v    = (const float*)d_in[10];
    const float* W_out  = (const float*)d_in[11];
    const float* b_out  = (const float*)d_in[12];
    float* out = (float*)d_out;

    float *p_value, *p_oa, *p_mid, *p_BtV, *p_BtOA, *p_BtO, *p_bOA;
    cudaGetSymbolAddress((void**)&p_value, g_value);
    cudaGetSymbolAddress((void**)&p_oa,    g_oa);
    cudaGetSymbolAddress((void**)&p_mid,   g_mid);
    cudaGetSymbolAddress((void**)&p_BtV,   g_BtV);
    cudaGetSymbolAddress((void**)&p_BtOA,  g_BtOA);
    cudaGetSymbolAddress((void**)&p_BtO,   g_BtO);
    cudaGetSymbolAddress((void**)&p_bOA,   g_bOA);

    const int smem_bytes = 4 * BUFW * 4;   // 73728
    cudaFuncSetAttribute(mma_gemm_kernel<true>,
                         cudaFuncAttributeMaxDynamicSharedMemorySize, smem_bytes);
    cudaFuncSetAttribute(mma_gemm_kernel<false>,
                         cudaFuncAttributeMaxDynamicSharedMemorySize, smem_bytes);

    // prep: weight transposes (tf32-rounded) + bias concat
    prep_kernel<<<193, dim3(32, 32)>>>(W_v, W_off, W_aw, W_out, b_off, b_aw);

    // fused GEMM1: value = flat@BtV + b_v  |  [off|aw] = query@BtOA + bOA
    mma_gemm_kernel<true><<<dim3(2, MV / 128 + MQ / 128), 256, smem_bytes>>>(
        flat, p_BtV, b_v, p_value, MV / 128,
        query, p_BtOA, p_bOA, p_oa);

    // sampling (2 queries per block; writes tf32-rounded g_mid)
    msda_sample_kernel<<<MQ / 2, 256>>>(refpts, shapes, start);

    // GEMM2: out = mid @ BtO + b_out (A already tf32 -> raw fragments)
    mma_gemm_kernel<false><<<dim3(2, MQ / 128), 256, smem_bytes>>>(
        p_mid, p_BtO, b_out, out, MQ / 128,
        p_mid, p_BtO, b_out, out);
}

// round 15
// speedup vs baseline: 1.1316x; 1.0696x over previous
#include <cuda_runtime.h>
#include <cuda_fp16.h>
#include <math.h>
#include <cstdint>

// ---------------- problem constants ----------------
#define NB      4
#define LQ      4096
#define DM      256
#define NH      8
#define NL      4
#define NP      4
#define DH      32
#define S_TOT   7680
#define HLP     128
#define MQ      (NB*LQ)     // 16384
#define MV      (NB*S_TOT)  // 30720

// ---------------- scratch (static device memory) ----------------
__device__ float  g_value[MV * DM];    // value = flat @ W_v (fp32)
__device__ float  g_oa  [MQ * 256];    // cols 0:128 = off, 128:256 = aw logits
__device__ __half g_mid [MQ * DM];     // sampled output (fp16, GEMM2 A operand)
__device__ __half g_BtV [256 * 256];   // W_v^T   [N,K] K-major, fp16
__device__ __half g_BtOA[256 * 256];   // [W_off^T ; W_aw^T],   fp16
__device__ __half g_BtO [256 * 256];   // W_out^T,              fp16
__device__ float  g_bOA [256];         // [b_off ; b_aw] (fp32)

// ---------------- helpers ----------------
__device__ __forceinline__ void mma_f16(float* c, const uint32_t* a,
                                        uint32_t b0, uint32_t b1) {
    asm volatile(
        "mma.sync.aligned.m16n8k16.row.col.f32.f16.f16.f32 "
        "{%0,%1,%2,%3}, {%4,%5,%6,%7}, {%8,%9}, {%0,%1,%2,%3};"
        : "+f"(c[0]), "+f"(c[1]), "+f"(c[2]), "+f"(c[3])
        : "r"(a[0]), "r"(a[1]), "r"(a[2]), "r"(a[3]), "r"(b0), "r"(b1));
}

// ldmatrix x4: four 8-row x 16B tiles; lane 4r+c <- (row r, word c) of its tile.
__device__ __forceinline__ void ldsm_x4(uint32_t* r, uint32_t addr) {
    asm volatile("ldmatrix.sync.aligned.m8n8.x4.shared.b16 {%0,%1,%2,%3}, [%4];"
                 : "=r"(r[0]), "=r"(r[1]), "=r"(r[2]), "=r"(r[3]) : "r"(addr));
}

__device__ __forceinline__ void cp16(uint32_t dst, const void* src) {
    asm volatile("cp.async.ca.shared.global [%0], [%1], 16;" :: "r"(dst), "l"(src));
}
#define CP_COMMIT() asm volatile("cp.async.commit_group;" ::: "memory")
#define CP_WAIT0()  asm volatile("cp.async.wait_group 0;"  ::: "memory")

__device__ __forceinline__ uint32_t h2u(__half2 h) {
    return *reinterpret_cast<uint32_t*>(&h);
}

// ---------------- fp16 mma.sync GEMM -----------------------------------------
// 128x128 tile, 256 threads (8 warps, warp tile 32x64), BK=32 halves,
// double-buffered. m16n8k16: 2 k-steps/iter, 16 MMA each (HALF the tf32 count).
// B always fp16 via cp.async. A: CVTA ? (LDG fp32 -> cvt f16x2 -> STS)
//                                   : fp16 cp.async (g_mid).
// RS_H=40 halves (80B rows): LDSM 8-row phases hit distinct 16B groups;
// cp.async 16B slots aligned (80*r % 16 == 0).
#define RS_H 40
#define BUFH (128 * RS_H)              // one matrix buffer: 5120 halves
template<bool CVTA>
__global__ __launch_bounds__(256)
void mma_gemm_kernel(const void* A0v, const __half* B0,
                     const float* bias0, float* C0, int rows0,
                     const void* A1v, const __half* B1,
                     const float* bias1, float* C1)
{
    extern __shared__ __half smh[];    // 2 stages x 2 matrices x BUFH = 40960 B

    const void* Av;  const __half* Bt;  const float* bias;  float* C;
    int block_row;
    if ((int)blockIdx.y < rows0) {
        Av = A0v; Bt = B0; bias = bias0; C = C0; block_row = blockIdx.y * 128;
    } else {
        Av = A1v; Bt = B1; bias = bias1; C = C1; block_row = (blockIdx.y - rows0) * 128;
    }

    const int tid  = threadIdx.x;
    const int wid  = tid >> 5;
    const int lane = tid & 31;
    const int g8   = lane >> 2;
    const int t4   = lane & 3;
    const int block_col = blockIdx.x * 128;
    const int warp_m = (wid >> 1) * 32;
    const int warp_n = (wid & 1) * 64;

    const float*  Agf = (const float*)Av  + (long)block_row * 256;  // CVTA
    const __half* Agh = (const __half*)Av + (long)block_row * 256;  // !CVTA
    const __half* Bg  = Bt + (long)block_col * 256;

    float acc[2][8][4];
    #pragma unroll
    for (int im = 0; im < 2; im++)
        #pragma unroll
        for (int in_ = 0; in_ < 8; in_++)
            #pragma unroll
            for (int q = 0; q < 4; q++)
                acc[im][in_][q] = 0.0f;

    uint32_t sbase;
    asm("{ .reg .u64 t; cvta.to.shared.u64 t, %1; cvt.u32.u64 %0, t; }"
        : "=r"(sbase) : "l"(smh));
    const uint32_t stage_bytes = (uint32_t)(2 * BUFH) * 2u;

    // fp16 cp.async mapping: 2 slots/thread per matrix-tile (128 rows x 4x16B)
    const int hr[2] = { tid >> 2, (tid + 256) >> 2 };
    const int hc    = (tid & 3) * 8;                // half-offset within row
    uint32_t hoff[2];
    #pragma unroll
    for (int j = 0; j < 2; j++)
        hoff[j] = (uint32_t)(hr[j] * RS_H + hc) * 2u;

    // fp32 A copy mapping (CVTA): 4 float4/thread
    const int cr[4] = { (tid + 0)   >> 3, (tid + 256) >> 3,
                        (tid + 512) >> 3, (tid + 768) >> 3 };
    const int cc = (tid & 7) * 4;
    uint32_t aoffc[4];
    #pragma unroll
    for (int j = 0; j < 4; j++)
        aoffc[j] = (uint32_t)(cr[j] * RS_H + cc) * 2u;

    // LDSM fragment addresses (byte offsets within a stage)
    // A (m16k16 per im): rows warp_m+im*16+(lane&15), k-col (lane>>4)*16B
    uint32_t aoff[2];
    #pragma unroll
    for (int im = 0; im < 2; im++)
        aoff[im] = (uint32_t)((warp_m + im * 16 + (lane & 15)) * RS_H) * 2u
                   + (uint32_t)(lane >> 4) * 16u;
    // B (two n-blocks per j): rows warp_n+j*16+(lane&7)+((lane>>4)*8),
    //                         k-col ((lane>>3)&1)*16B; B matrix at +BUFH halves
    uint32_t boff[4];
    #pragma unroll
    for (int j = 0; j < 4; j++)
        boff[j] = (uint32_t)BUFH * 2u
                  + (uint32_t)((warp_n + j * 16 + (lane & 7) + ((lane >> 4) * 8)) * RS_H) * 2u
                  + (uint32_t)((lane >> 3) & 1) * 16u;

    float4 ra[4];

    // ---- prologue: stage k-chunk 0 into stage 0 ----
    #pragma unroll
    for (int j = 0; j < 2; j++)
        cp16(sbase + BUFH * 2u + hoff[j], Bg + (long)hr[j] * 256 + hc);
    if (!CVTA) {
        #pragma unroll
        for (int j = 0; j < 2; j++)
            cp16(sbase + hoff[j], Agh + (long)hr[j] * 256 + hc);
        CP_COMMIT();
    } else {
        CP_COMMIT();
        #pragma unroll
        for (int j = 0; j < 4; j++)
            ra[j] = *(const float4*)(Agf + (long)cr[j] * 256 + cc);
        #pragma unroll
        for (int j = 0; j < 4; j++) {
            uint2 u;
            u.x = h2u(__floats2half2_rn(ra[j].x, ra[j].y));
            u.y = h2u(__floats2half2_rn(ra[j].z, ra[j].w));
            *(uint2*)((char*)smh + aoffc[j]) = u;
        }
    }
    CP_WAIT0();
    __syncthreads();

    for (int it = 0; it < 8; ++it) {
        const uint32_t buf = sbase + (uint32_t)(it & 1) * stage_bytes;
        const uint32_t nb  = sbase + (uint32_t)((it + 1) & 1) * stage_bytes;

        if (it < 7) {
            const int k0 = (it + 1) * 32;
            #pragma unroll
            for (int j = 0; j < 2; j++)
                cp16(nb + BUFH * 2u + hoff[j], Bg + (long)hr[j] * 256 + k0 + hc);
            if (!CVTA) {
                #pragma unroll
                for (int j = 0; j < 2; j++)
                    cp16(nb + hoff[j], Agh + (long)hr[j] * 256 + k0 + hc);
                CP_COMMIT();
            } else {
                CP_COMMIT();
                #pragma unroll
                for (int j = 0; j < 4; j++)
                    ra[j] = *(const float4*)(Agf + (long)cr[j] * 256 + k0 + cc);
            }
        }

        #pragma unroll
        for (int ks = 0; ks < 2; ks++) {
            const uint32_t kb = (uint32_t)ks * 32u;   // 16 halves per k-step
            uint32_t af[2][4];
            ldsm_x4(af[0], buf + aoff[0] + kb);
            ldsm_x4(af[1], buf + aoff[1] + kb);
            #pragma unroll
            for (int j = 0; j < 4; j++) {
                uint32_t bf[4];
                ldsm_x4(bf, buf + boff[j] + kb);
                mma_f16(acc[0][2 * j    ], af[0], bf[0], bf[1]);
                mma_f16(acc[0][2 * j + 1], af[0], bf[2], bf[3]);
                mma_f16(acc[1][2 * j    ], af[1], bf[0], bf[1]);
                mma_f16(acc[1][2 * j + 1], af[1], bf[2], bf[3]);
            }
        }

        if (it < 7) {
            if (CVTA) {
                char* nbp = (char*)smh + (uint32_t)((it + 1) & 1) * stage_bytes;
                #pragma unroll
                for (int j = 0; j < 4; j++) {
                    uint2 u;
                    u.x = h2u(__floats2half2_rn(ra[j].x, ra[j].y));
                    u.y = h2u(__floats2half2_rn(ra[j].z, ra[j].w));
                    *(uint2*)(nbp + aoffc[j]) = u;
                }
            }
            CP_WAIT0();
            __syncthreads();
        }
    }

    #pragma unroll
    for (int im = 0; im < 2; im++) {
        const int r0 = block_row + warp_m + im * 16 + g8;
        #pragma unroll
        for (int in_ = 0; in_ < 8; in_++) {
            const int col = block_col + warp_n + in_ * 8 + 2 * t4;
            const float bx = bias[col], by = bias[col + 1];
            float2 o0 = make_float2(acc[im][in_][0] + bx, acc[im][in_][1] + by);
            float2 o1 = make_float2(acc[im][in_][2] + bx, acc[im][in_][3] + by);
            *(float2*)(C + (long)r0 * 256 + col)       = o0;
            *(float2*)(C + (long)(r0 + 8) * 256 + col) = o1;
        }
    }
}

// ---------------- fused prep: 4 transposes (fp16) + bias concat --------------
__global__ void prep_kernel(const float* __restrict__ W_v,
                            const float* __restrict__ W_off,
                            const float* __restrict__ W_aw,
                            const float* __restrict__ W_out,
                            const float* __restrict__ b_off,
                            const float* __restrict__ b_aw)
{
    const int b = blockIdx.x;
    if (b == 192) {
        int t = threadIdx.y * 32 + threadIdx.x;
        if (t < 256) g_bOA[t] = (t < 128) ? b_off[t] : b_aw[t - 128];
        return;
    }
    const float* W; __half* Bt; int N, rowoff, local;
    if (b < 64)       { W = W_v;   Bt = g_BtV;  N = 256; rowoff = 0;   local = b; }
    else if (b < 96)  { W = W_off; Bt = g_BtOA; N = 128; rowoff = 0;   local = b - 64; }
    else if (b < 128) { W = W_aw;  Bt = g_BtOA; N = 128; rowoff = 128; local = b - 96; }
    else              { W = W_out; Bt = g_BtO;  N = 256; rowoff = 0;   local = b - 128; }
    const int nx = N / 32;
    const int n0 = (local % nx) * 32;
    const int k0 = (local / nx) * 32;

    __shared__ float t[32][33];
    t[threadIdx.y][threadIdx.x] = W[(k0 + threadIdx.y) * N + n0 + threadIdx.x];
    __syncthreads();
    Bt[(long)(rowoff + n0 + threadIdx.y) * 256 + k0 + threadIdx.x] =
        __float2half_rn(t[threadIdx.x][threadIdx.y]);
}

// ---------------- sampling kernel (R12 structure; fp16 g_mid store) ----------
__global__ __launch_bounds__(256)
void msda_sample_kernel(const float* __restrict__ ref,
                        const int*   __restrict__ shapes,
                        const int*   __restrict__ start)
{
    __shared__ float4 sp[2][NH][16];

    const int q0  = blockIdx.x * 2;
    const int tid = threadIdx.x;

    {
        const int ql = tid >> 7;
        const int t  = tid & 127;
        const int nq = q0 + ql;
        const int n  = nq / LQ;
        const int m  = t >> 4;
        const int lp = t & 15;
        const int l  = lp >> 2;

        const int   Ti = shapes[l];
        const float Tf = (float)Ti;
        const int   st = start[l];

        const float offv  = g_oa[(long)nq * 256 +       m * 16 + lp];
        const float logit = g_oa[(long)nq * 256 + 128 + m * 16 + lp];
        const float r     = ref[(long)nq * NL + l];

        float x  = fminf(fmaxf(r * Tf + offv - 0.5f, 0.0f), Tf - 1.0f);
        float x0 = floorf(x);
        float w  = x - x0;
        int   i0 = (int)x0;
        int   i1 = min(i0 + 1, Ti - 1);
        int   g0 = (n * S_TOT + st + i0) * DM + m * DH;
        int   g1 = (n * S_TOT + st + i1) * DM + m * DH;

        float e = expf(logit);
        float ssum = e;
        #pragma unroll
        for (int o = 8; o > 0; o >>= 1)
            ssum += __shfl_xor_sync(0xffffffffu, ssum, o, 16);
        float aw = e / ssum;

        sp[ql][m][lp] = make_float4(__int_as_float(g0), __int_as_float(g1), w, aw);
    }
    __syncthreads();

    const int wid  = tid >> 5;
    const int lane = tid & 31;
    const int qw   = wid >> 2;
    const int nq2  = q0 + qw;
    const int g    = lane >> 3;
    const int c    = lane & 7;

    #pragma unroll
    for (int h2 = 0; h2 < 2; h2++) {
        const int mh = (wid & 3) * 2 + h2;
        float4 acc = make_float4(0.f, 0.f, 0.f, 0.f);
        #pragma unroll
        for (int t = 0; t < 4; t++) {
            float4 pr = sp[qw][mh][t * 4 + g];
            int   ig0 = __float_as_int(pr.x);
            int   ig1 = __float_as_int(pr.y);
            float w   = pr.z;
            float aw  = pr.w;
            float4 v0 = *(const float4*)(g_value + ig0 + c * 4);
            float4 v1 = *(const float4*)(g_value + ig1 + c * 4);
            acc.x = fmaf(aw, fmaf(w, v1.x - v0.x, v0.x), acc.x);
            acc.y = fmaf(aw, fmaf(w, v1.y - v0.y, v0.y), acc.y);
            acc.z = fmaf(aw, fmaf(w, v1.z - v0.z, v0.z), acc.z);
            acc.w = fmaf(aw, fmaf(w, v1.w - v0.w, v0.w), acc.w);
        }
        #pragma unroll
        for (int o = 8; o <= 16; o <<= 1) {
            acc.x += __shfl_xor_sync(0xffffffffu, acc.x, o);
            acc.y += __shfl_xor_sync(0xffffffffu, acc.y, o);
            acc.z += __shfl_xor_sync(0xffffffffu, acc.z, o);
            acc.w += __shfl_xor_sync(0xffffffffu, acc.w, o);
        }
        if (lane < 8) {
            uint2 u;
            __half2 h0 = __floats2half2_rn(acc.x, acc.y);
            __half2 h1 = __floats2half2_rn(acc.z, acc.w);
            u.x = *reinterpret_cast<uint32_t*>(&h0);
            u.y = *reinterpret_cast<uint32_t*>(&h1);
            *(uint2*)(g_mid + (long)nq2 * DM + mh * DH + c * 4) = u;
        }
    }
}

// ---------------- launch ------------------------------------------------------
extern "C" void kernel_launch(void* const* d_in, const int* in_sizes, int n_in,
                              void* d_out, int out_size)
{
    const float* query  = (const float*)d_in[0];
    const float* refpts = (const float*)d_in[1];
    const float* flat   = (const float*)d_in[2];
    const int*   shapes = (const int*)  d_in[3];
    const int*   start  = (const int*)  d_in[4];
    const float* W_off  = (const float*)d_in[5];
    const float* b_off  = (const float*)d_in[6];
    const float* W_aw   = (const float*)d_in[7];
    const float* b_aw   = (const float*)d_in[8];
    const float* W_v    = (const float*)d_in[9];
    const float* b_v    = (const float*)d_in[10];
    const float* W_out  = (const float*)d_in[11];
    const float* b_out  = (const float*)d_in[12];
    float* out = (float*)d_out;

    float *p_value, *p_oa, *p_bOA;
    __half *p_mid, *p_BtV, *p_BtOA, *p_BtO;
    cudaGetSymbolAddress((void**)&p_value, g_value);
    cudaGetSymbolAddress((void**)&p_oa,    g_oa);
    cudaGetSymbolAddress((void**)&p_mid,   g_mid);
    cudaGetSymbolAddress((void**)&p_BtV,   g_BtV);
    cudaGetSymbolAddress((void**)&p_BtOA,  g_BtOA);
    cudaGetSymbolAddress((void**)&p_BtO,   g_BtO);
    cudaGetSymbolAddress((void**)&p_bOA,   g_bOA);

    const int smem_bytes = 4 * BUFH * 2;   // 40960
    cudaFuncSetAttribute(mma_gemm_kernel<true>,
                         cudaFuncAttributeMaxDynamicSharedMemorySize, smem_bytes);
    cudaFuncSetAttribute(mma_gemm_kernel<false>,
                         cudaFuncAttributeMaxDynamicSharedMemorySize, smem_bytes);

    // prep: weight transposes (fp16) + bias concat
    prep_kernel<<<193, dim3(32, 32)>>>(W_v, W_off, W_aw, W_out, b_off, b_aw);

    // fused GEMM1: value = flat@BtV + b_v  |  [off|aw] = query@BtOA + bOA
    mma_gemm_kernel<true><<<dim3(2, MV / 128 + MQ / 128), 256, smem_bytes>>>(
        flat, p_BtV, b_v, p_value, MV / 128,
        query, p_BtOA, p_bOA, p_oa);

    // sampling (2 queries per block; writes fp16 g_mid)
    msda_sample_kernel<<<MQ / 2, 256>>>(refpts, shapes, start);

    // GEMM2: out = mid @ BtO + b_out (A fp16 -> pure cp.async)
    mma_gemm_kernel<false><<<dim3(2, MQ / 128), 256, smem_bytes>>>(
        p_mid, p_BtO, b_out, out, MQ / 128,
        p_mid, p_BtO, b_out, out);
}

// round 16
// speedup vs baseline: 1.1895x; 1.0512x over previous
#include <cuda_runtime.h>
#include <cuda_fp16.h>
#include <math.h>
#include <cstdint>

// ---------------- problem constants ----------------
#define NB      4
#define LQ      4096
#define DM      256
#define NH      8
#define NL      4
#define NP      4
#define DH      32
#define S_TOT   7680
#define HLP     128
#define MQ      (NB*LQ)     // 16384
#define MV      (NB*S_TOT)  // 30720

// ---------------- scratch (static device memory) ----------------
__device__ __half g_value[MV * DM];    // value = flat @ W_v (fp16)
__device__ float  g_oa  [MQ * 256];    // cols 0:128 = off, 128:256 = aw logits
__device__ __half g_mid [MQ * DM];     // sampled output (fp16, GEMM2 A operand)
__device__ __half g_BtV [256 * 256];   // W_v^T   [N,K] K-major, fp16
__device__ __half g_BtOA[256 * 256];   // [W_off^T ; W_aw^T],   fp16
__device__ __half g_BtO [256 * 256];   // W_out^T,              fp16
__device__ float  g_bOA [256];         // [b_off ; b_aw] (fp32)

// ---------------- helpers ----------------
__device__ __forceinline__ void mma_f16(float* c, const uint32_t* a,
                                        uint32_t b0, uint32_t b1) {
    asm volatile(
        "mma.sync.aligned.m16n8k16.row.col.f32.f16.f16.f32 "
        "{%0,%1,%2,%3}, {%4,%5,%6,%7}, {%8,%9}, {%0,%1,%2,%3};"
        : "+f"(c[0]), "+f"(c[1]), "+f"(c[2]), "+f"(c[3])
        : "r"(a[0]), "r"(a[1]), "r"(a[2]), "r"(a[3]), "r"(b0), "r"(b1));
}

__device__ __forceinline__ void ldsm_x4(uint32_t* r, uint32_t addr) {
    asm volatile("ldmatrix.sync.aligned.m8n8.x4.shared.b16 {%0,%1,%2,%3}, [%4];"
                 : "=r"(r[0]), "=r"(r[1]), "=r"(r[2]), "=r"(r[3]) : "r"(addr));
}

__device__ __forceinline__ void cp16(uint32_t dst, const void* src) {
    asm volatile("cp.async.ca.shared.global [%0], [%1], 16;" :: "r"(dst), "l"(src));
}
#define CP_COMMIT() asm volatile("cp.async.commit_group;" ::: "memory")
#define CP_WAIT0()  asm volatile("cp.async.wait_group 0;"  ::: "memory")

__device__ __forceinline__ uint32_t h2u(__half2 h) {
    return *reinterpret_cast<uint32_t*>(&h);
}

// ---------------- fp16 mma.sync GEMM -----------------------------------------
// 128x128 tile, 256 threads (8 warps, warp tile 32x64), BK=32 halves,
// double-buffered. B always fp16 via cp.async.
// A: CVTA ? (LDG fp32 -> cvt f16x2 -> STS) : fp16 cp.async.
// HC0: GEMM0's C output stored as fp16 (half2 stores); GEMM1/other fp32.
// RS_H=40 halves (80B rows): LDSM 8-row phases conflict-free.
#define RS_H 40
#define BUFH (128 * RS_H)              // one matrix buffer: 5120 halves
template<bool CVTA, bool HC0>
__global__ __launch_bounds__(256)
void mma_gemm_kernel(const void* A0v, const __half* B0,
                     const float* bias0, void* C0v, int rows0,
                     const void* A1v, const __half* B1,
                     const float* bias1, float* C1)
{
    extern __shared__ __half smh[];    // 2 stages x 2 matrices x BUFH = 40960 B

    const void* Av;  const __half* Bt;  const float* bias;  void* Cv;
    int block_row;
    bool isg0;
    if ((int)blockIdx.y < rows0) {
        Av = A0v; Bt = B0; bias = bias0; Cv = C0v; block_row = blockIdx.y * 128;
        isg0 = true;
    } else {
        Av = A1v; Bt = B1; bias = bias1; Cv = (void*)C1;
        block_row = (blockIdx.y - rows0) * 128;
        isg0 = false;
    }

    const int tid  = threadIdx.x;
    const int wid  = tid >> 5;
    const int lane = tid & 31;
    const int g8   = lane >> 2;
    const int t4   = lane & 3;
    const int block_col = blockIdx.x * 128;
    const int warp_m = (wid >> 1) * 32;
    const int warp_n = (wid & 1) * 64;

    const float*  Agf = (const float*)Av  + (long)block_row * 256;  // CVTA
    const __half* Agh = (const __half*)Av + (long)block_row * 256;  // !CVTA
    const __half* Bg  = Bt + (long)block_col * 256;

    float acc[2][8][4];
    #pragma unroll
    for (int im = 0; im < 2; im++)
        #pragma unroll
        for (int in_ = 0; in_ < 8; in_++)
            #pragma unroll
            for (int q = 0; q < 4; q++)
                acc[im][in_][q] = 0.0f;

    uint32_t sbase;
    asm("{ .reg .u64 t; cvta.to.shared.u64 t, %1; cvt.u32.u64 %0, t; }"
        : "=r"(sbase) : "l"(smh));
    const uint32_t stage_bytes = (uint32_t)(2 * BUFH) * 2u;

    // fp16 cp.async mapping: 2 slots/thread per matrix-tile
    const int hr[2] = { tid >> 2, (tid + 256) >> 2 };
    const int hc    = (tid & 3) * 8;
    uint32_t hoff[2];
    #pragma unroll
    for (int j = 0; j < 2; j++)
        hoff[j] = (uint32_t)(hr[j] * RS_H + hc) * 2u;

    // fp32 A copy mapping (CVTA): 4 float4/thread
    const int cr[4] = { (tid + 0)   >> 3, (tid + 256) >> 3,
                        (tid + 512) >> 3, (tid + 768) >> 3 };
    const int cc = (tid & 7) * 4;
    uint32_t aoffc[4];
    #pragma unroll
    for (int j = 0; j < 4; j++)
        aoffc[j] = (uint32_t)(cr[j] * RS_H + cc) * 2u;

    // LDSM fragment addresses (byte offsets within a stage)
    uint32_t aoff[2];
    #pragma unroll
    for (int im = 0; im < 2; im++)
        aoff[im] = (uint32_t)((warp_m + im * 16 + (lane & 15)) * RS_H) * 2u
                   + (uint32_t)(lane >> 4) * 16u;
    uint32_t boff[4];
    #pragma unroll
    for (int j = 0; j < 4; j++)
        boff[j] = (uint32_t)BUFH * 2u
                  + (uint32_t)((warp_n + j * 16 + (lane & 7) + ((lane >> 4) * 8)) * RS_H) * 2u
                  + (uint32_t)((lane >> 3) & 1) * 16u;

    float4 ra[4];

    // ---- prologue: stage k-chunk 0 into stage 0 ----
    #pragma unroll
    for (int j = 0; j < 2; j++)
        cp16(sbase + BUFH * 2u + hoff[j], Bg + (long)hr[j] * 256 + hc);
    if (!CVTA) {
        #pragma unroll
        for (int j = 0; j < 2; j++)
            cp16(sbase + hoff[j], Agh + (long)hr[j] * 256 + hc);
        CP_COMMIT();
    } else {
        CP_COMMIT();
        #pragma unroll
        for (int j = 0; j < 4; j++)
            ra[j] = *(const float4*)(Agf + (long)cr[j] * 256 + cc);
        #pragma unroll
        for (int j = 0; j < 4; j++) {
            uint2 u;
            u.x = h2u(__floats2half2_rn(ra[j].x, ra[j].y));
            u.y = h2u(__floats2half2_rn(ra[j].z, ra[j].w));
            *(uint2*)((char*)smh + aoffc[j]) = u;
        }
    }
    CP_WAIT0();
    __syncthreads();

    for (int it = 0; it < 8; ++it) {
        const uint32_t buf = sbase + (uint32_t)(it & 1) * stage_bytes;
        const uint32_t nb  = sbase + (uint32_t)((it + 1) & 1) * stage_bytes;

        if (it < 7) {
            const int k0 = (it + 1) * 32;
            #pragma unroll
            for (int j = 0; j < 2; j++)
                cp16(nb + BUFH * 2u + hoff[j], Bg + (long)hr[j] * 256 + k0 + hc);
            if (!CVTA) {
                #pragma unroll
                for (int j = 0; j < 2; j++)
                    cp16(nb + hoff[j], Agh + (long)hr[j] * 256 + k0 + hc);
                CP_COMMIT();
            } else {
                CP_COMMIT();
                #pragma unroll
                for (int j = 0; j < 4; j++)
                    ra[j] = *(const float4*)(Agf + (long)cr[j] * 256 + k0 + cc);
            }
        }

        #pragma unroll
        for (int ks = 0; ks < 2; ks++) {
            const uint32_t kb = (uint32_t)ks * 32u;
            uint32_t af[2][4];
            ldsm_x4(af[0], buf + aoff[0] + kb);
            ldsm_x4(af[1], buf + aoff[1] + kb);
            #pragma unroll
            for (int j = 0; j < 4; j++) {
                uint32_t bf[4];
                ldsm_x4(bf, buf + boff[j] + kb);
                mma_f16(acc[0][2 * j    ], af[0], bf[0], bf[1]);
                mma_f16(acc[0][2 * j + 1], af[0], bf[2], bf[3]);
                mma_f16(acc[1][2 * j    ], af[1], bf[0], bf[1]);
                mma_f16(acc[1][2 * j + 1], af[1], bf[2], bf[3]);
            }
        }

        if (it < 7) {
            if (CVTA) {
                char* nbp = (char*)smh + (uint32_t)((it + 1) & 1) * stage_bytes;
                #pragma unroll
                for (int j = 0; j < 4; j++) {
                    uint2 u;
                    u.x = h2u(__floats2half2_rn(ra[j].x, ra[j].y));
                    u.y = h2u(__floats2half2_rn(ra[j].z, ra[j].w));
                    *(uint2*)(nbp + aoffc[j]) = u;
                }
            }
            CP_WAIT0();
            __syncthreads();
        }
    }

    if (HC0 && isg0) {
        __half* Ch = (__half*)Cv;
        #pragma unroll
        for (int im = 0; im < 2; im++) {
            const int r0 = block_row + warp_m + im * 16 + g8;
            #pragma unroll
            for (int in_ = 0; in_ < 8; in_++) {
                const int col = block_col + warp_n + in_ * 8 + 2 * t4;
                const float bx = bias[col], by = bias[col + 1];
                *(uint32_t*)(Ch + (long)r0 * 256 + col) =
                    h2u(__floats2half2_rn(acc[im][in_][0] + bx, acc[im][in_][1] + by));
                *(uint32_t*)(Ch + (long)(r0 + 8) * 256 + col) =
                    h2u(__floats2half2_rn(acc[im][in_][2] + bx, acc[im][in_][3] + by));
            }
        }
    } else {
        float* Cf = (float*)Cv;
        #pragma unroll
        for (int im = 0; im < 2; im++) {
            const int r0 = block_row + warp_m + im * 16 + g8;
            #pragma unroll
            for (int in_ = 0; in_ < 8; in_++) {
                const int col = block_col + warp_n + in_ * 8 + 2 * t4;
                const float bx = bias[col], by = bias[col + 1];
                float2 o0 = make_float2(acc[im][in_][0] + bx, acc[im][in_][1] + by);
                float2 o1 = make_float2(acc[im][in_][2] + bx, acc[im][in_][3] + by);
                *(float2*)(Cf + (long)r0 * 256 + col)       = o0;
                *(float2*)(Cf + (long)(r0 + 8) * 256 + col) = o1;
            }
        }
    }
}

// ---------------- fused prep: 4 transposes (fp16) + bias concat --------------
__global__ void prep_kernel(const float* __restrict__ W_v,
                            const float* __restrict__ W_off,
                            const float* __restrict__ W_aw,
                            const float* __restrict__ W_out,
                            const float* __restrict__ b_off,
                            const float* __restrict__ b_aw)
{
    const int b = blockIdx.x;
    if (b == 192) {
        int t = threadIdx.y * 32 + threadIdx.x;
        if (t < 256) g_bOA[t] = (t < 128) ? b_off[t] : b_aw[t - 128];
        return;
    }
    const float* W; __half* Bt; int N, rowoff, local;
    if (b < 64)       { W = W_v;   Bt = g_BtV;  N = 256; rowoff = 0;   local = b; }
    else if (b < 96)  { W = W_off; Bt = g_BtOA; N = 128; rowoff = 0;   local = b - 64; }
    else if (b < 128) { W = W_aw;  Bt = g_BtOA; N = 128; rowoff = 128; local = b - 96; }
    else              { W = W_out; Bt = g_BtO;  N = 256; rowoff = 0;   local = b - 128; }
    const int nx = N / 32;
    const int n0 = (local % nx) * 32;
    const int k0 = (local / nx) * 32;

    __shared__ float t[32][33];
    t[threadIdx.y][threadIdx.x] = W[(k0 + threadIdx.y) * N + n0 + threadIdx.x];
    __syncthreads();
    Bt[(long)(rowoff + n0 + threadIdx.y) * 256 + k0 + threadIdx.x] =
        __float2half_rn(t[threadIdx.x][threadIdx.y]);
}

// ---------------- sampling kernel (R12 structure; fp16 gathers + stores) -----
__global__ __launch_bounds__(256)
void msda_sample_kernel(const float* __restrict__ ref,
                        const int*   __restrict__ shapes,
                        const int*   __restrict__ start)
{
    __shared__ float4 sp[2][NH][16];

    const int q0  = blockIdx.x * 2;
    const int tid = threadIdx.x;

    {
        const int ql = tid >> 7;
        const int t  = tid & 127;
        const int nq = q0 + ql;
        const int n  = nq / LQ;
        const int m  = t >> 4;
        const int lp = t & 15;
        const int l  = lp >> 2;

        const int   Ti = shapes[l];
        const float Tf = (float)Ti;
        const int   st = start[l];

        const float offv  = g_oa[(long)nq * 256 +       m * 16 + lp];
        const float logit = g_oa[(long)nq * 256 + 128 + m * 16 + lp];
        const float r     = ref[(long)nq * NL + l];

        float x  = fminf(fmaxf(r * Tf + offv - 0.5f, 0.0f), Tf - 1.0f);
        float x0 = floorf(x);
        float w  = x - x0;
        int   i0 = (int)x0;
        int   i1 = min(i0 + 1, Ti - 1);
        int   g0 = (n * S_TOT + st + i0) * DM + m * DH;
        int   g1 = (n * S_TOT + st + i1) * DM + m * DH;

        float e = expf(logit);
        float ssum = e;
        #pragma unroll
        for (int o = 8; o > 0; o >>= 1)
            ssum += __shfl_xor_sync(0xffffffffu, ssum, o, 16);
        float aw = e / ssum;

        sp[ql][m][lp] = make_float4(__int_as_float(g0), __int_as_float(g1), w, aw);
    }
    __syncthreads();

    const int wid  = tid >> 5;
    const int lane = tid & 31;
    const int qw   = wid >> 2;
    const int nq2  = q0 + qw;
    const int g    = lane >> 3;
    const int c    = lane & 7;

    #pragma unroll
    for (int h2 = 0; h2 < 2; h2++) {
        const int mh = (wid & 3) * 2 + h2;
        float4 acc = make_float4(0.f, 0.f, 0.f, 0.f);
        #pragma unroll
        for (int t = 0; t < 4; t++) {
            float4 pr = sp[qw][mh][t * 4 + g];
            int   ig0 = __float_as_int(pr.x);
            int   ig1 = __float_as_int(pr.y);
            float w   = pr.z;
            float aw  = pr.w;
            uint2 u0 = *(const uint2*)(g_value + ig0 + c * 4);   // 4 halves
            uint2 u1 = *(const uint2*)(g_value + ig1 + c * 4);
            float2 v0a = __half22float2(*reinterpret_cast<__half2*>(&u0.x));
            float2 v0b = __half22float2(*reinterpret_cast<__half2*>(&u0.y));
            float2 v1a = __half22float2(*reinterpret_cast<__half2*>(&u1.x));
            float2 v1b = __half22float2(*reinterpret_cast<__half2*>(&u1.y));
            acc.x = fmaf(aw, fmaf(w, v1a.x - v0a.x, v0a.x), acc.x);
            acc.y = fmaf(aw, fmaf(w, v1a.y - v0a.y, v0a.y), acc.y);
            acc.z = fmaf(aw, fmaf(w, v1b.x - v0b.x, v0b.x), acc.z);
            acc.w = fmaf(aw, fmaf(w, v1b.y - v0b.y, v0b.y), acc.w);
        }
        #pragma unroll
        for (int o = 8; o <= 16; o <<= 1) {
            acc.x += __shfl_xor_sync(0xffffffffu, acc.x, o);
            acc.y += __shfl_xor_sync(0xffffffffu, acc.y, o);
            acc.z += __shfl_xor_sync(0xffffffffu, acc.z, o);
            acc.w += __shfl_xor_sync(0xffffffffu, acc.w, o);
        }
        if (lane < 8) {
            uint2 u;
            u.x = h2u(__floats2half2_rn(acc.x, acc.y));
            u.y = h2u(__floats2half2_rn(acc.z, acc.w));
            *(uint2*)(g_mid + (long)nq2 * DM + mh * DH + c * 4) = u;
        }
    }
}

// ---------------- launch ------------------------------------------------------
extern "C" void kernel_launch(void* const* d_in, const int* in_sizes, int n_in,
                              void* d_out, int out_size)
{
    const float* query  = (const float*)d_in[0];
    const float* refpts = (const float*)d_in[1];
    const float* flat   = (const float*)d_in[2];
    const int*   shapes = (const int*)  d_in[3];
    const int*   start  = (const int*)  d_in[4];
    const float* W_off  = (const float*)d_in[5];
    const float* b_off  = (const float*)d_in[6];
    const float* W_aw   = (const float*)d_in[7];
    const float* b_aw   = (const float*)d_in[8];
    const float* W_v    = (const float*)d_in[9];
    const float* b_v    = (const float*)d_in[10];
    const float* W_out  = (const float*)d_in[11];
    const float* b_out  = (const float*)d_in[12];
    float* out = (float*)d_out;

    float *p_oa, *p_bOA;
    __half *p_value, *p_mid, *p_BtV, *p_BtOA, *p_BtO;
    cudaGetSymbolAddress((void**)&p_value, g_value);
    cudaGetSymbolAddress((void**)&p_oa,    g_oa);
    cudaGetSymbolAddress((void**)&p_mid,   g_mid);
    cudaGetSymbolAddress((void**)&p_BtV,   g_BtV);
    cudaGetSymbolAddress((void**)&p_BtOA,  g_BtOA);
    cudaGetSymbolAddress((void**)&p_BtO,   g_BtO);
    cudaGetSymbolAddress((void**)&p_bOA,   g_bOA);

    const int smem_bytes = 4 * BUFH * 2;   // 40960
    cudaFuncSetAttribute((void*)mma_gemm_kernel<true, true>,
                         cudaFuncAttributeMaxDynamicSharedMemorySize, smem_bytes);
    cudaFuncSetAttribute((void*)mma_gemm_kernel<false, false>,
                         cudaFuncAttributeMaxDynamicSharedMemorySize, smem_bytes);

    // prep: weight transposes (fp16) + bias concat
    prep_kernel<<<193, dim3(32, 32)>>>(W_v, W_off, W_aw, W_out, b_off, b_aw);

    // fused GEMM1: value = flat@BtV + b_v (fp16 out)  |  [off|aw] (fp32 out)
    mma_gemm_kernel<true, true><<<dim3(2, MV / 128 + MQ / 128), 256, smem_bytes>>>(
        flat, p_BtV, b_v, p_value, MV / 128,
        query, p_BtOA, p_bOA, p_oa);

    // sampling (2 queries per block; fp16 gathers; writes fp16 g_mid)
    msda_sample_kernel<<<MQ / 2, 256>>>(refpts, shapes, start);

    // GEMM2: out = mid @ BtO + b_out (A fp16 -> pure cp.async, fp32 out)
    mma_gemm_kernel<false, false><<<dim3(2, MQ / 128), 256, smem_bytes>>>(
        p_mid, p_BtO, b_out, out, MQ / 128,
        p_mid, p_BtO, b_out, out);
}